// round 14
// baseline (speedup 1.0000x reference)
#include <cuda_runtime.h>
#include <math.h>

// s = sum_i R[i] * ||Z[i,:]||^2 ; out = 1 - exp(-exp(s))
// Z: [N,128] fp32 row-major (256 MB), R: [N] fp32 (2 MB). HBM-bound reduction.
//
// Hybrid: 87.5% static grid-stride bulk (barrier-free, proven R8 loop) +
// 12.5% warp-stolen tail pool (absorbs the L2-die-variance finish-time spread).
// NO __syncthreads in the work path. Deterministic: every partial has a fixed
// slot (per-warp for bulk, per-chunk for tail); final sum is fixed-order double.

#define NTHREADS  256
#define NBLOCKS   1184                    // 148x8: one resident wave at <=32 regs
#define NWARPS    (NBLOCKS * NTHREADS / 32)   // 9472
#define TCHUNK4   1024                    // tail chunk: 1024 float4 = 16 KB
#define MAXTAIL   4096

static __device__ float        g_warp_partials[NWARPS];
static __device__ float        g_tail[MAXTAIL];
static __device__ unsigned int g_next   = 0;   // tail chunk counter (wraps -> 0)
static __device__ unsigned int g_arrive = 0;   // warp arrival counter (wraps -> 0)

__global__ __launch_bounds__(NTHREADS, 8) void bp_fused_kernel(
    const float* __restrict__ Z, const float* __restrict__ R, int nrows,
    float* __restrict__ out)
{
    const float4* __restrict__ Z4 = reinterpret_cast<const float4*>(Z);
    const int total4 = nrows * 32;                       // 32 float4 per row
    int ntail = (total4 / 8) / TCHUNK4;                  // ~12.5% of work
    if (ntail > MAXTAIL) ntail = MAXTAIL;
    const int bulk4  = total4 - ntail * TCHUNK4;

    const int stride = gridDim.x * blockDim.x;
    const int tid    = blockIdx.x * blockDim.x + threadIdx.x;
    const int lane   = threadIdx.x & 31;
    const int gwid   = tid >> 5;                         // global warp id

    float a0 = 0.f, a1 = 0.f, a2 = 0.f, a3 = 0.f;

    // ---------------- Phase 1: static bulk (barrier-free, x4 unroll) ----------
    int j = tid;
    for (; j + 3 * stride < bulk4; j += 4 * stride) {
        float4 v0 = __ldcs(&Z4[j]);
        float4 v1 = __ldcs(&Z4[j +     stride]);
        float4 v2 = __ldcs(&Z4[j + 2 * stride]);
        float4 v3 = __ldcs(&Z4[j + 3 * stride]);
        float  r0 = __ldg(&R[(j             ) >> 5]);
        float  r1 = __ldg(&R[(j +     stride) >> 5]);
        float  r2 = __ldg(&R[(j + 2 * stride) >> 5]);
        float  r3 = __ldg(&R[(j + 3 * stride) >> 5]);
        a0 = fmaf(v0.x*v0.x + v0.y*v0.y + v0.z*v0.z + v0.w*v0.w, r0, a0);
        a1 = fmaf(v1.x*v1.x + v1.y*v1.y + v1.z*v1.z + v1.w*v1.w, r1, a1);
        a2 = fmaf(v2.x*v2.x + v2.y*v2.y + v2.z*v2.z + v2.w*v2.w, r2, a2);
        a3 = fmaf(v3.x*v3.x + v3.y*v3.y + v3.z*v3.z + v3.w*v3.w, r3, a3);
    }
    for (; j < bulk4; j += stride) {
        float4 v = __ldcs(&Z4[j]);
        a0 = fmaf(v.x*v.x + v.y*v.y + v.z*v.z + v.w*v.w, __ldg(&R[j >> 5]), a0);
    }

    {   // per-warp bulk partial -> fixed slot
        float acc = (a0 + a1) + (a2 + a3);
        #pragma unroll
        for (int o = 16; o > 0; o >>= 1)
            acc += __shfl_xor_sync(0xffffffffu, acc, o);
        if (lane == 0) g_warp_partials[gwid] = acc;
    }

    // ---------------- Phase 2: warp-level stolen tail chunks ------------------
    const unsigned grab_limit = (unsigned)ntail + NWARPS - 1;   // wraps to 0 exactly
    for (;;) {
        unsigned c = 0;
        if (lane == 0) c = atomicInc(&g_next, grab_limit);
        c = __shfl_sync(0xffffffffu, c, 0);
        if (c >= (unsigned)ntail) break;

        const int base = bulk4 + (int)c * TCHUNK4;
        float t0 = 0.f, t1 = 0.f, t2 = 0.f, t3 = 0.f;
        #pragma unroll
        for (int it = 0; it < TCHUNK4 / 128; it++) {     // 8 iters x 4 loads/lane
            int j0 = base + it * 128 + lane;
            if (j0 + 96 < total4) {
                float4 v0 = __ldcs(&Z4[j0]);
                float4 v1 = __ldcs(&Z4[j0 + 32]);
                float4 v2 = __ldcs(&Z4[j0 + 64]);
                float4 v3 = __ldcs(&Z4[j0 + 96]);
                float  r0 = __ldg(&R[(j0     ) >> 5]);
                float  r1 = __ldg(&R[(j0 + 32) >> 5]);
                float  r2 = __ldg(&R[(j0 + 64) >> 5]);
                float  r3 = __ldg(&R[(j0 + 96) >> 5]);
                t0 = fmaf(v0.x*v0.x + v0.y*v0.y + v0.z*v0.z + v0.w*v0.w, r0, t0);
                t1 = fmaf(v1.x*v1.x + v1.y*v1.y + v1.z*v1.z + v1.w*v1.w, r1, t1);
                t2 = fmaf(v2.x*v2.x + v2.y*v2.y + v2.z*v2.z + v2.w*v2.w, r2, t2);
                t3 = fmaf(v3.x*v3.x + v3.y*v3.y + v3.z*v3.z + v3.w*v3.w, r3, t3);
            } else {
                #pragma unroll
                for (int q = 0; q < 4; q++) {
                    int jq = j0 + 32 * q;
                    if (jq < total4) {
                        float4 v = __ldcs(&Z4[jq]);
                        t0 = fmaf(v.x*v.x + v.y*v.y + v.z*v.z + v.w*v.w,
                                  __ldg(&R[jq >> 5]), t0);
                    }
                }
            }
        }
        float tacc = (t0 + t1) + (t2 + t3);
        #pragma unroll
        for (int o = 16; o > 0; o >>= 1)
            tacc += __shfl_xor_sync(0xffffffffu, tacc, o);
        if (lane == 0) g_tail[c] = tacc;                 // fixed slot per chunk
    }

    // ---------------- Finalize: last-arriving warp, fixed-order sum -----------
    __threadfence();
    unsigned prev = 0;
    if (lane == 0) prev = atomicInc(&g_arrive, NWARPS - 1);  // wraps -> auto-reset
    prev = __shfl_sync(0xffffffffu, prev, 0);
    if (prev != NWARPS - 1) return;

    __threadfence();                                     // acquire side
    double d0 = 0.0, d1 = 0.0, d2 = 0.0, d3 = 0.0;
    for (int i = lane; i + 96 < NWARPS; i += 128) {
        d0 += (double)g_warp_partials[i];
        d1 += (double)g_warp_partials[i + 32];
        d2 += (double)g_warp_partials[i + 64];
        d3 += (double)g_warp_partials[i + 96];
    }
    for (int i = (NWARPS / 128) * 128 + lane; i < NWARPS; i += 32)
        d0 += (double)g_warp_partials[i];
    for (int i = lane; i < ntail; i += 32)
        d1 += (double)g_tail[i];

    double dacc = (d0 + d1) + (d2 + d3);
    #pragma unroll
    for (int o = 16; o > 0; o >>= 1)
        dacc += __shfl_xor_sync(0xffffffffu, dacc, o);

    if (lane == 0) {
        double lam = exp(dacc);
        out[0] = (float)(1.0 - exp(-lam));
    }
}

extern "C" void kernel_launch(void* const* d_in, const int* in_sizes, int n_in,
                              void* d_out, int out_size)
{
    const float* a0 = (const float*)d_in[0];
    const float* a1 = (const float*)d_in[1];
    const float* Z; const float* R; int nrows;
    if (in_sizes[0] >= in_sizes[1]) { Z = a0; R = a1; nrows = in_sizes[1]; }
    else                            { Z = a1; R = a0; nrows = in_sizes[0]; }

    bp_fused_kernel<<<NBLOCKS, NTHREADS>>>(Z, R, nrows, (float*)d_out);
}

// round 15
// speedup vs baseline: 1.7898x; 1.7898x over previous
#include <cuda_runtime.h>
#include <math.h>

// s = sum_i R[i] * ||Z[i,:]||^2 ; out = 1 - exp(-exp(s))
// Z: [N,128] fp32 row-major (256 MB), R: [N] fp32 (2 MB). HBM-bound reduction.
// Single fused kernel, single resident wave. GB300 has 152 SMs: one wave at
// 8 CTAs/SM (32 regs) = 1216 CTAs. Static grid-stride, barrier-free mainloop,
// last-block finalize. Plain LDG for Z (measured faster than __ldcs here).

#define NBLOCKS  1216                   // 152 SMs x 8 CTAs -- one full wave
#define NTHREADS 256

static __device__ float        g_partials[NBLOCKS];
static __device__ unsigned int g_arrive = 0;   // wraps back to 0 each launch

__global__ __launch_bounds__(NTHREADS, 8) void bp_fused_kernel(
    const float* __restrict__ Z, const float* __restrict__ R, int nrows,
    float* __restrict__ out)
{
    const float4* __restrict__ Z4 = reinterpret_cast<const float4*>(Z);
    const int total4 = nrows * 32;                    // 32 float4 per 128-wide row
    const int stride = gridDim.x * blockDim.x;        // threads in grid
    const int tid    = blockIdx.x * blockDim.x + threadIdx.x;

    float a0 = 0.f, a1 = 0.f, a2 = 0.f, a3 = 0.f;

    int j = tid;
    // Unroll x4, independent accumulators -> 4 front-batched LDG.128 + 4 R loads
    // in flight per trip. Regs stay <=32 so 8 CTAs/SM remain resident.
    for (; j + 3 * stride < total4; j += 4 * stride) {
        float4 v0 = Z4[j];
        float4 v1 = Z4[j +     stride];
        float4 v2 = Z4[j + 2 * stride];
        float4 v3 = Z4[j + 3 * stride];
        float  r0 = __ldg(&R[(j             ) >> 5]);
        float  r1 = __ldg(&R[(j +     stride) >> 5]);
        float  r2 = __ldg(&R[(j + 2 * stride) >> 5]);
        float  r3 = __ldg(&R[(j + 3 * stride) >> 5]);
        a0 = fmaf(v0.x*v0.x + v0.y*v0.y + v0.z*v0.z + v0.w*v0.w, r0, a0);
        a1 = fmaf(v1.x*v1.x + v1.y*v1.y + v1.z*v1.z + v1.w*v1.w, r1, a1);
        a2 = fmaf(v2.x*v2.x + v2.y*v2.y + v2.z*v2.z + v2.w*v2.w, r2, a2);
        a3 = fmaf(v3.x*v3.x + v3.y*v3.y + v3.z*v3.z + v3.w*v3.w, r3, a3);
    }
    for (; j < total4; j += stride) {
        float4 v = Z4[j];
        float  r = __ldg(&R[j >> 5]);
        a0 = fmaf(v.x*v.x + v.y*v.y + v.z*v.z + v.w*v.w, r, a0);
    }

    float acc = (a0 + a1) + (a2 + a3);

    // warp reduce
    #pragma unroll
    for (int o = 16; o > 0; o >>= 1)
        acc += __shfl_xor_sync(0xffffffffu, acc, o);

    __shared__ float smem[NTHREADS / 32];
    if ((threadIdx.x & 31) == 0) smem[threadIdx.x >> 5] = acc;
    __syncthreads();

    if (threadIdx.x < 32) {
        float v = (threadIdx.x < NTHREADS / 32) ? smem[threadIdx.x] : 0.f;
        #pragma unroll
        for (int o = (NTHREADS / 32) / 2; o > 0; o >>= 1)
            v += __shfl_xor_sync(0xffffffffu, v, o);
        if (threadIdx.x == 0) g_partials[blockIdx.x] = v;
    }

    // ---- last block finalizes (deterministic: fixed-order sum of partials) ----
    __shared__ bool is_last;
    __threadfence();                                  // partials visible grid-wide
    if (threadIdx.x == 0) {
        unsigned int prev = atomicInc(&g_arrive, NBLOCKS - 1); // wraps -> auto-reset
        is_last = (prev == NBLOCKS - 1);
    }
    __syncthreads();
    if (!is_last) return;

    double dacc = 0.0;
    for (int i = threadIdx.x; i < NBLOCKS; i += NTHREADS)
        dacc += (double)g_partials[i];

    #pragma unroll
    for (int o = 16; o > 0; o >>= 1)
        dacc += __shfl_xor_sync(0xffffffffu, dacc, o);

    __shared__ double dsmem[NTHREADS / 32];
    if ((threadIdx.x & 31) == 0) dsmem[threadIdx.x >> 5] = dacc;
    __syncthreads();

    if (threadIdx.x == 0) {
        double s = 0.0;
        #pragma unroll
        for (int w = 0; w < NTHREADS / 32; w++) s += dsmem[w];
        double lam = exp(s);
        out[0] = (float)(1.0 - exp(-lam));
    }
}

extern "C" void kernel_launch(void* const* d_in, const int* in_sizes, int n_in,
                              void* d_out, int out_size)
{
    const float* a0 = (const float*)d_in[0];
    const float* a1 = (const float*)d_in[1];
    const float* Z; const float* R; int nrows;
    if (in_sizes[0] >= in_sizes[1]) { Z = a0; R = a1; nrows = in_sizes[1]; }
    else                            { Z = a1; R = a0; nrows = in_sizes[0]; }

    bp_fused_kernel<<<NBLOCKS, NTHREADS>>>(Z, R, nrows, (float*)d_out);
}